// round 12
// baseline (speedup 1.0000x reference)
#include <cuda_runtime.h>
#include <cuda_bf16.h>
#include <cstdint>

// Problem constants
#define SD      16384        // S*D
#define NJ      22           // 14 alpha cols + 8 beta cols
#define NJP     24           // padded (2 zero cols)
#define BN      2048         // B*N
#define KC      8            // k-chunks (2048 floats each, == s)
#define MT      16           // m-tiles of 128 bn
#define NTILE   32           // 64-k tiles per chunk
#define KT_TOT  256          // total 64-k tiles (SD/64)
#define NSTAGE  4
#define STAGE_B 32768        // 8 warps * 4KB per stage
#define WTILE_B 4096         // per-warp per-stage bytes (16 rows x 64 k x 4B)

typedef unsigned long long ull;

// g_Wf: B operand pre-baked in mma.m16n8k16 B-fragment layout.
// [kt][ks 0..3][ng 0..2][lane 0..31] -> uint2 {b0, b1}:
//   j = ng*8 + lane/4,  k0 = kt*64 + ks*16 + (lane%4)*2
//   b0 = bf16x2( w[j][k0],   w[j][k0+1] )
//   b1 = bf16x2( w[j][k0+8], w[j][k0+9] )
// with w[j][k] = (gamma[k]+1) * W[k][j], j>=22 -> 0.
__device__ __align__(16) uint2 g_Wf[KT_TOT * 12 * 32];
__device__ float g_part[KC][BN][NJP];
__device__ float g_ss[KC][BN];
__device__ float g_M[BN * 64];

__device__ __forceinline__ uint32_t pack_bf16x2(float lo, float hi) {
    __nv_bfloat162 h = __float22bfloat162_rn(make_float2(lo, hi));
    return *reinterpret_cast<uint32_t*>(&h);
}
__device__ __forceinline__ uint32_t smem_u32(const void* p) {
    uint32_t a;
    asm("{ .reg .u64 t; cvta.to.shared.u64 t, %1; cvt.u32.u64 %0, t; }" : "=r"(a) : "l"(p));
    return a;
}
__device__ __forceinline__ void cp_async16(uint32_t saddr, const void* gptr) {
    asm volatile("cp.async.cg.shared.global [%0], [%1], 16;\n" :: "r"(saddr), "l"(gptr));
}
__device__ __forceinline__ void mma_bf16(float* d, const uint32_t* a, uint2 b) {
    asm volatile(
        "mma.sync.aligned.m16n8k16.row.col.f32.bf16.bf16.f32 "
        "{%0,%1,%2,%3}, {%4,%5,%6,%7}, {%8,%9}, {%0,%1,%2,%3};"
        : "+f"(d[0]), "+f"(d[1]), "+f"(d[2]), "+f"(d[3])
        : "r"(a[0]), "r"(a[1]), "r"(a[2]), "r"(a[3]), "r"(b.x), "r"(b.y));
}

// ---------------------------------------------------------------------------
// Kernel P: bake B fragments (gamma folded, bf16). One thread per uint2.
// ---------------------------------------------------------------------------
__global__ void k_prepW(const float* __restrict__ gamma,
                        const float* __restrict__ Wa,
                        const float* __restrict__ Wb) {
    int i = blockIdx.x * blockDim.x + threadIdx.x;
    if (i >= KT_TOT * 12 * 32) return;
    int kt   = i / 384;
    int rem  = i - kt * 384;
    int ks   = rem / 96;
    int ng   = (rem / 32) % 3;
    int lane = rem & 31;
    int quad = lane >> 2, pos = lane & 3;
    int j  = ng * 8 + quad;
    int k0 = kt * 64 + ks * 16 + pos * 2;

    float w[4] = {0.f, 0.f, 0.f, 0.f};
    if (j < 22) {
        #pragma unroll
        for (int e = 0; e < 4; e++) {
            int k = k0 + (e >> 1) * 8 + (e & 1);
            float ww = (j < 14) ? Wa[(size_t)k * 14 + j] : Wb[(size_t)k * 8 + (j - 14)];
            w[e] = (gamma[k] + 1.0f) * ww;
        }
    }
    g_Wf[i] = make_uint2(pack_bf16x2(w[0], w[1]), pack_bf16x2(w[2], w[3]));
}

// ---------------------------------------------------------------------------
// Kernel A: bf16 mma.sync reductions with a 4-stage cp.async smem FIFO.
// grid=(MT, KC) = 128 CTAs, 256 threads (1 CTA/SM, 128KB dyn smem).
// Each warp owns 16 bn rows; per 64-k tile it cp.asyncs its 4KB slice into
// smem with destination addresses permuted into FRAGMENT-CONSUME order:
// slot byte = (ks*4 + hi*2 + delta)*256 + lane*8 holds floats (k, k+1) for
// that lane's (quad,pos) fragment -> LDS.64 conflict-free, zero index math.
// Pipeline depth 3 tiles (~2000cyc) hides DRAM latency without registers.
// ---------------------------------------------------------------------------
__global__ __launch_bounds__(256) void k_reduce(const float* __restrict__ resid) {
    extern __shared__ __align__(16) char smem[];
    const int warp = threadIdx.x >> 5;
    const int lane = threadIdx.x & 31;
    const int quad = lane >> 2, pos = lane & 3;
    const int mt = blockIdx.x, c = blockIdx.y;
    const int b = mt >> 3, nbase = (mt & 7) * 128;

    const uint32_t wsm = smem_u32(smem) + warp * WTILE_B;   // stage 0 base

    // ---- precompute loader src (16B-unit offsets) and consume-order dst ----
    // v = i*32 + lane: r = v>>4 (row 0..15), u16 = v&15 (16B unit within row)
    const float4* r16 = reinterpret_cast<const float4*>(resid);
    size_t  srcu[8];
    uint32_t gdst[8];
    const size_t base16 = ((size_t)(b * 8 + c) * 1024 + nbase + warp * 16) * 512;
    #pragma unroll
    for (int i = 0; i < 8; i++) {
        int v = i * 32 + lane;
        int r = v >> 4, u16 = v & 15;
        srcu[i] = base16 + (size_t)r * 512 + u16;           // + t*16 per tile
        int ks = u16 >> 2, dl = (u16 >> 1) & 1, hi = r >> 3;
        int q = r & 7, pos0 = (u16 & 1) * 2;
        gdst[i] = (uint32_t)((ks * 4 + hi * 2 + dl) * 256 + q * 32 + pos0 * 8);
    }

    float acc[3][4];
    #pragma unroll
    for (int ng = 0; ng < 3; ng++)
        #pragma unroll
        for (int e = 0; e < 4; e++) acc[ng][e] = 0.0f;
    float ss_lo = 0.0f, ss_hi = 0.0f;

    // ---- prologue: stages 0..2 ----
    #pragma unroll
    for (int p = 0; p < 3; p++) {
        const uint32_t sb = wsm + p * STAGE_B;
        #pragma unroll
        for (int i = 0; i < 8; i++)
            cp_async16(sb + gdst[i], r16 + srcu[i] + p * 16);
        asm volatile("cp.async.commit_group;\n");
    }

    #pragma unroll 1
    for (int t = 0; t < NTILE; t++) {
        // issue tile t+3 (or an empty group to keep the count aligned)
        if (t + 3 < NTILE) {
            const uint32_t sb = wsm + ((t + 3) & 3) * STAGE_B;
            #pragma unroll
            for (int i = 0; i < 8; i++)
                cp_async16(sb + gdst[i], r16 + srcu[i] + (t + 3) * 16);
        }
        asm volatile("cp.async.commit_group;\n");
        asm volatile("cp.async.wait_group 3;\n");
        __syncthreads();

        // B fragments (L2-hot, shared by all CTAs/warps)
        uint2 bv[12];
        const uint2* wt = g_Wf + (size_t)(c * NTILE + t) * 384 + lane;
        #pragma unroll
        for (int i = 0; i < 12; i++) bv[i] = wt[i * 32];

        const char* sb = smem + warp * WTILE_B + (t & 3) * STAGE_B + lane * 8;
        #pragma unroll
        for (int ks = 0; ks < 4; ks++) {
            // consume-order slots: +0 = (lo,d0), +256 = (lo,d1), +512 = (hi,d0), +768 = (hi,d1)
            float2 v0 = *reinterpret_cast<const float2*>(sb + (ks * 4 + 0) * 256);
            float2 v2 = *reinterpret_cast<const float2*>(sb + (ks * 4 + 1) * 256);
            float2 v1 = *reinterpret_cast<const float2*>(sb + (ks * 4 + 2) * 256);
            float2 v3 = *reinterpret_cast<const float2*>(sb + (ks * 4 + 3) * 256);
            // fp32 sumsq
            ss_lo = fmaf(v0.x, v0.x, ss_lo);
            ss_lo = fmaf(v0.y, v0.y, ss_lo);
            ss_lo = fmaf(v2.x, v2.x, ss_lo);
            ss_lo = fmaf(v2.y, v2.y, ss_lo);
            ss_hi = fmaf(v1.x, v1.x, ss_hi);
            ss_hi = fmaf(v1.y, v1.y, ss_hi);
            ss_hi = fmaf(v3.x, v3.x, ss_hi);
            ss_hi = fmaf(v3.y, v3.y, ss_hi);
            // cvt -> bf16 A fragment
            uint32_t a[4];
            a[0] = pack_bf16x2(v0.x, v0.y);
            a[1] = pack_bf16x2(v1.x, v1.y);
            a[2] = pack_bf16x2(v2.x, v2.y);
            a[3] = pack_bf16x2(v3.x, v3.y);
            #pragma unroll
            for (int ng = 0; ng < 3; ng++)
                mma_bf16(acc[ng], a, bv[ks * 3 + ng]);
        }
        __syncthreads();   // all warps done with stage t&3 before its reuse
    }

    // store dot partials: D frag (m16n8): c0,c1 -> row quad, cols pos*2,+1
    const int bn_lo = mt * 128 + warp * 16 + quad;
    #pragma unroll
    for (int ng = 0; ng < 3; ng++) {
        const int j0 = ng * 8 + pos * 2;
        *reinterpret_cast<float2*>(&g_part[c][bn_lo][j0]) =
            make_float2(acc[ng][0], acc[ng][1]);
        *reinterpret_cast<float2*>(&g_part[c][bn_lo + 8][j0]) =
            make_float2(acc[ng][2], acc[ng][3]);
    }
    // sumsq: reduce across the 4 lanes sharing this quad
    #pragma unroll
    for (int o = 1; o < 4; o <<= 1) {
        ss_lo += __shfl_xor_sync(0xffffffffu, ss_lo, o, 4);
        ss_hi += __shfl_xor_sync(0xffffffffu, ss_hi, o, 4);
    }
    if (pos == 0) {
        g_ss[c][bn_lo]     = ss_lo;
        g_ss[c][bn_lo + 8] = ss_hi;
    }
}

// ---------------------------------------------------------------------------
// Kernel B: per-(b,n) scalar epilogue -> 8x8 mixing matrix M
// ---------------------------------------------------------------------------
__global__ void k_mix(const float* __restrict__ salpha,
                      const float* __restrict__ pbs,
                      const float* __restrict__ rscale,
                      const float* __restrict__ sbeta,
                      const float* __restrict__ hps) {
    int bn = blockIdx.x * blockDim.x + threadIdx.x;
    if (bn >= BN) return;

    float dot[NJ];
    #pragma unroll
    for (int j = 0; j < NJ; j++) {
        float v = 0.0f;
        #pragma unroll
        for (int c = 0; c < KC; c++) v += g_part[c][bn][j];
        dot[j] = v;
    }
    float sumsq = 0.0f;
    #pragma unroll
    for (int c = 0; c < KC; c++) sumsq += g_ss[c][bn];

    float scale = rsqrtf(fmaxf(sumsq, 1e-24f)) * 128.0f;  // sqrt(16384)=128
    float ps = pbs[0], rs = rscale[0], hp = hps[0];

    // w_pre = softmax(ps * dyn_pre + static_alpha[:8])
    float l[8], mx = -1e30f;
    #pragma unroll
    for (int i = 0; i < 8; i++) {
        l[i] = ps * (scale * dot[i]) + salpha[i];
        mx = fmaxf(mx, l[i]);
    }
    float e[8], sum = 0.0f;
    #pragma unroll
    for (int i = 0; i < 8; i++) { e[i] = expf(l[i] - mx); sum += e[i]; }
    float inv_sum = 1.0f / sum;
    float wpre[8];
    #pragma unroll
    for (int i = 0; i < 8; i++) wpre[i] = e[i] * inv_sum;

    // pairwise softmax first elements
    float p[3];
    #pragma unroll
    for (int k = 0; k < 3; k++) {
        float c0 = rs * (scale * dot[8 + 2 * k])     + salpha[8 + 2 * k];
        float c1 = rs * (scale * dot[8 + 2 * k + 1]) + salpha[8 + 2 * k + 1];
        p[k] = 1.0f / (1.0f + expf(c1 - c0));
    }
    // Kron: H[s][t] = h[s^t]
    float h[8];
    #pragma unroll
    for (int x = 0; x < 8; x++) {
        float f0 = (x & 4) ? (1.0f - p[0]) : p[0];
        float f1 = (x & 2) ? (1.0f - p[1]) : p[1];
        float f2 = (x & 1) ? (1.0f - p[2]) : p[2];
        h[x] = f0 * f1 * f2;
    }
    float beta[8];
    #pragma unroll
    for (int t = 0; t < 8; t++)
        beta[t] = 1.0f / (1.0f + expf(-(hp * (scale * dot[14 + t]) + sbeta[t])));

    float* Mo = &g_M[bn * 64];
    #pragma unroll
    for (int s = 0; s < 8; s++)
        #pragma unroll
        for (int t = 0; t < 8; t++)
            Mo[s * 8 + t] = h[s ^ t] + beta[t] * wpre[s];
}

// ---------------------------------------------------------------------------
// Kernel C: out[t,d] = sum_s M[s][t] * r[s,d].  grid=(BN, 2). fp32 residuals.
// ---------------------------------------------------------------------------
__global__ __launch_bounds__(256) void k_apply(const float* __restrict__ resid,
                                               float* __restrict__ out) {
    const int bn = blockIdx.x;
    const int b = bn >> 10, n = bn & 1023;

    __shared__ float Ms[64];
    if (threadIdx.x < 64) Ms[threadIdx.x] = g_M[bn * 64 + threadIdx.x];
    __syncthreads();

    float M[64];
    #pragma unroll
    for (int i = 0; i < 64; i++) M[i] = Ms[i];

    const size_t base = (size_t)b * 16777216u + (size_t)n * 2048u;
    const int d = blockIdx.y * 1024 + threadIdx.x * 4;

    float4 acc[8];
    #pragma unroll
    for (int t = 0; t < 8; t++) acc[t] = make_float4(0.f, 0.f, 0.f, 0.f);

    #pragma unroll
    for (int s = 0; s < 8; s++) {
        float4 r4 = *reinterpret_cast<const float4*>(resid + base + (size_t)s * 2097152u + d);
        #pragma unroll
        for (int t = 0; t < 8; t++) {
            float m = M[s * 8 + t];
            acc[t].x += m * r4.x;
            acc[t].y += m * r4.y;
            acc[t].z += m * r4.z;
            acc[t].w += m * r4.w;
        }
    }
    #pragma unroll
    for (int t = 0; t < 8; t++)
        *reinterpret_cast<float4*>(out + base + (size_t)t * 2097152u + d) = acc[t];
}

// ---------------------------------------------------------------------------
extern "C" void kernel_launch(void* const* d_in, const int* in_sizes, int n_in,
                              void* d_out, int out_size) {
    const float* resid  = (const float*)d_in[0];   // residuals (B*S, N, D)
    const float* gamma  = (const float*)d_in[1];   // (S*D,)
    const float* salpha = (const float*)d_in[2];   // (S+T,) = 14
    const float* Wa     = (const float*)d_in[3];   // (S*D, 14)
    const float* pbs    = (const float*)d_in[4];   // (1,)
    const float* rs     = (const float*)d_in[5];   // (1,)
    const float* sbeta  = (const float*)d_in[6];   // (S,) = 8
    const float* Wb     = (const float*)d_in[7];   // (S*D, 8)
    const float* hps    = (const float*)d_in[8];   // scalar
    float* out = (float*)d_out;

    const int smem_bytes = NSTAGE * STAGE_B;       // 128 KB
    cudaFuncSetAttribute(k_reduce, cudaFuncAttributeMaxDynamicSharedMemorySize,
                         smem_bytes);

    k_prepW<<<(KT_TOT * 12 * 32 + 255) / 256, 256>>>(gamma, Wa, Wb);
    k_reduce<<<dim3(MT, KC), 256, smem_bytes>>>(resid);
    k_mix<<<BN / 256, 256>>>(salpha, pbs, rs, sbeta, hps);
    k_apply<<<dim3(BN, 2), 256>>>(resid, out);
}

// round 13
// speedup vs baseline: 1.1811x; 1.1811x over previous
#include <cuda_runtime.h>
#include <cuda_bf16.h>
#include <cstdint>

// Problem constants
#define SD      16384        // S*D
#define NJ      22           // 14 alpha cols + 8 beta cols
#define NJP     24           // padded (2 zero cols)
#define BN      2048         // B*N
#define KC      8            // k-chunks (2048 floats each, == s)
#define MT      16           // m-tiles of 128 bn
#define NTILE   32           // 64-k tiles per chunk
#define KT_TOT  256          // total 64-k tiles (SD/64)

typedef unsigned long long ull;

// g_Wf: B fragments baked with the PERMUTED k mapping (must match A loads):
// fragment f = ks*3+ng, lane (quad,pos):  j = ng*8 + quad,
//   kphys = kt*64 + ks*16 + pos*4
//   b0 = bf16x2( w[j][kphys],   w[j][kphys+1] )
//   b1 = bf16x2( w[j][kphys+2], w[j][kphys+3] )
// Packed two fragments per uint4: g_Wf[kt*192 + u*32 + lane] holds
// {f=2u: b0, b1, f=2u+1: b0, b1}.  w[j][k] = (gamma[k]+1)*W[k][j], j>=22 -> 0.
__device__ __align__(16) uint4 g_Wf[KT_TOT * 6 * 32];
__device__ float g_part[KC][BN][NJP];
__device__ float g_ss[KC][BN];
__device__ float g_M[BN * 64];

__device__ __forceinline__ uint32_t pack_bf16x2(float lo, float hi) {
    __nv_bfloat162 h = __float22bfloat162_rn(make_float2(lo, hi));
    return *reinterpret_cast<uint32_t*>(&h);
}

__device__ __forceinline__ void mma_bf16(float* d, const uint32_t* a,
                                         uint32_t b0, uint32_t b1) {
    asm volatile(
        "mma.sync.aligned.m16n8k16.row.col.f32.bf16.bf16.f32 "
        "{%0,%1,%2,%3}, {%4,%5,%6,%7}, {%8,%9}, {%0,%1,%2,%3};"
        : "+f"(d[0]), "+f"(d[1]), "+f"(d[2]), "+f"(d[3])
        : "r"(a[0]), "r"(a[1]), "r"(a[2]), "r"(a[3]), "r"(b0), "r"(b1));
}

// ---------------------------------------------------------------------------
// Kernel P: bake B fragments (gamma folded, bf16, permuted k). One thread
// per uint4 output: KT_TOT * 6 * 32 = 49152 threads.
// ---------------------------------------------------------------------------
__global__ void k_prepW(const float* __restrict__ gamma,
                        const float* __restrict__ Wa,
                        const float* __restrict__ Wb) {
    int i = blockIdx.x * blockDim.x + threadIdx.x;
    if (i >= KT_TOT * 6 * 32) return;
    int kt   = i / 192;
    int rem  = i - kt * 192;
    int u    = rem >> 5;
    int lane = rem & 31;
    int quad = lane >> 2, pos = lane & 3;

    uint32_t vals[4];
    #pragma unroll
    for (int h = 0; h < 2; h++) {
        int f  = 2 * u + h;
        int ks = f / 3, ng = f % 3;
        int j  = ng * 8 + quad;
        int kphys = kt * 64 + ks * 16 + pos * 4;
        float w[4] = {0.f, 0.f, 0.f, 0.f};
        if (j < 22) {
            #pragma unroll
            for (int e = 0; e < 4; e++) {
                int k = kphys + e;
                float ww = (j < 14) ? Wa[(size_t)k * 14 + j]
                                    : Wb[(size_t)k * 8 + (j - 14)];
                w[e] = (gamma[k] + 1.0f) * ww;
            }
        }
        vals[2 * h]     = pack_bf16x2(w[0], w[1]);
        vals[2 * h + 1] = pack_bf16x2(w[2], w[3]);
    }
    g_Wf[i] = make_uint4(vals[0], vals[1], vals[2], vals[3]);
}

// ---------------------------------------------------------------------------
// Kernel A: bf16 mma.sync reductions, float4 A-loads with permuted-k B.
// grid=(MT, KC) = 128 CTAs, 256 threads. Warp w owns rows [w*16, w*16+16)
// of the 128-bn m-tile, scanning 2048 k. Per tile: 8 LDG.128 for A
// (halved wavefronts vs LDG.64) + 6 LDG.128 for B (L1/L2-hot).
// No smem, no syncs.
// ---------------------------------------------------------------------------
__global__ __launch_bounds__(256) void k_reduce(const float* __restrict__ resid) {
    const int warp = threadIdx.x >> 5;
    const int lane = threadIdx.x & 31;
    const int quad = lane >> 2, pos = lane & 3;
    const int mt = blockIdx.x, c = blockIdx.y;
    const int b = mt >> 3, nbase = (mt & 7) * 128;

    const int row_lo = warp * 16 + quad;       // fragment rows quad / quad+8
    const float4* r4 = reinterpret_cast<const float4*>(resid);
    // float4-index bases: (b*16777216 + c*2097152 + row*2048)/4 + pos
    const uint32_t off_lo = (uint32_t)b * 4194304u + (uint32_t)c * 524288u
                          + (uint32_t)(nbase + row_lo) * 512u + (uint32_t)pos;
    const uint32_t off_hi = off_lo + 8u * 512u;

    float acc[3][4];
    #pragma unroll
    for (int ng = 0; ng < 3; ng++)
        #pragma unroll
        for (int e = 0; e < 4; e++) acc[ng][e] = 0.0f;
    float ss_lo = 0.0f, ss_hi = 0.0f;

    #pragma unroll 1
    for (int t = 0; t < NTILE; t++) {
        // A loads: 8 independent LDG.128 (quad->8 rows, pos->64B run)
        float4 lo[4], hi[4];
        const uint32_t kb = (uint32_t)t * 16u;
        #pragma unroll
        for (int ks = 0; ks < 4; ks++) {
            lo[ks] = r4[off_lo + kb + ks * 4];
            hi[ks] = r4[off_hi + kb + ks * 4];
        }
        // B fragments: 6 coalesced LDG.128 (shared by all warps/CTAs)
        uint4 bv[6];
        const uint4* wt = g_Wf + (size_t)(c * NTILE + t) * 192 + lane;
        #pragma unroll
        for (int i = 0; i < 6; i++) bv[i] = wt[i * 32];
        uint32_t bf[12][2];
        #pragma unroll
        for (int i = 0; i < 6; i++) {
            bf[2 * i][0]     = bv[i].x; bf[2 * i][1]     = bv[i].y;
            bf[2 * i + 1][0] = bv[i].z; bf[2 * i + 1][1] = bv[i].w;
        }

        #pragma unroll
        for (int ks = 0; ks < 4; ks++) {
            float4 vl = lo[ks], vh = hi[ks];
            // fp32 sumsq from the same registers
            ss_lo = fmaf(vl.x, vl.x, ss_lo);
            ss_lo = fmaf(vl.y, vl.y, ss_lo);
            ss_lo = fmaf(vl.z, vl.z, ss_lo);
            ss_lo = fmaf(vl.w, vl.w, ss_lo);
            ss_hi = fmaf(vh.x, vh.x, ss_hi);
            ss_hi = fmaf(vh.y, vh.y, ss_hi);
            ss_hi = fmaf(vh.z, vh.z, ss_hi);
            ss_hi = fmaf(vh.w, vh.w, ss_hi);
            // cvt -> bf16 A fragment (permuted k: a0/a2 = first/second pair)
            uint32_t a[4];
            a[0] = pack_bf16x2(vl.x, vl.y);
            a[1] = pack_bf16x2(vh.x, vh.y);
            a[2] = pack_bf16x2(vl.z, vl.w);
            a[3] = pack_bf16x2(vh.z, vh.w);
            #pragma unroll
            for (int ng = 0; ng < 3; ng++) {
                const int f = ks * 3 + ng;
                mma_bf16(acc[ng], a, bf[f][0], bf[f][1]);
            }
        }
    }

    // store dot partials: D frag (m16n8): c0,c1 -> row quad, cols pos*2,+1
    const int bn_lo = mt * 128 + row_lo;
    #pragma unroll
    for (int ng = 0; ng < 3; ng++) {
        const int j0 = ng * 8 + pos * 2;
        *reinterpret_cast<float2*>(&g_part[c][bn_lo][j0]) =
            make_float2(acc[ng][0], acc[ng][1]);
        *reinterpret_cast<float2*>(&g_part[c][bn_lo + 8][j0]) =
            make_float2(acc[ng][2], acc[ng][3]);
    }
    // sumsq: reduce across the 4 lanes sharing this quad
    #pragma unroll
    for (int o = 1; o < 4; o <<= 1) {
        ss_lo += __shfl_xor_sync(0xffffffffu, ss_lo, o, 4);
        ss_hi += __shfl_xor_sync(0xffffffffu, ss_hi, o, 4);
    }
    if (pos == 0) {
        g_ss[c][bn_lo]     = ss_lo;
        g_ss[c][bn_lo + 8] = ss_hi;
    }
}

// ---------------------------------------------------------------------------
// Kernel B: per-(b,n) scalar epilogue -> 8x8 mixing matrix M
// ---------------------------------------------------------------------------
__global__ void k_mix(const float* __restrict__ salpha,
                      const float* __restrict__ pbs,
                      const float* __restrict__ rscale,
                      const float* __restrict__ sbeta,
                      const float* __restrict__ hps) {
    int bn = blockIdx.x * blockDim.x + threadIdx.x;
    if (bn >= BN) return;

    float dot[NJ];
    #pragma unroll
    for (int j = 0; j < NJ; j++) {
        float v = 0.0f;
        #pragma unroll
        for (int c = 0; c < KC; c++) v += g_part[c][bn][j];
        dot[j] = v;
    }
    float sumsq = 0.0f;
    #pragma unroll
    for (int c = 0; c < KC; c++) sumsq += g_ss[c][bn];

    float scale = rsqrtf(fmaxf(sumsq, 1e-24f)) * 128.0f;  // sqrt(16384)=128
    float ps = pbs[0], rs = rscale[0], hp = hps[0];

    // w_pre = softmax(ps * dyn_pre + static_alpha[:8])
    float l[8], mx = -1e30f;
    #pragma unroll
    for (int i = 0; i < 8; i++) {
        l[i] = ps * (scale * dot[i]) + salpha[i];
        mx = fmaxf(mx, l[i]);
    }
    float e[8], sum = 0.0f;
    #pragma unroll
    for (int i = 0; i < 8; i++) { e[i] = expf(l[i] - mx); sum += e[i]; }
    float inv_sum = 1.0f / sum;
    float wpre[8];
    #pragma unroll
    for (int i = 0; i < 8; i++) wpre[i] = e[i] * inv_sum;

    // pairwise softmax first elements
    float p[3];
    #pragma unroll
    for (int k = 0; k < 3; k++) {
        float c0 = rs * (scale * dot[8 + 2 * k])     + salpha[8 + 2 * k];
        float c1 = rs * (scale * dot[8 + 2 * k + 1]) + salpha[8 + 2 * k + 1];
        p[k] = 1.0f / (1.0f + expf(c1 - c0));
    }
    // Kron: H[s][t] = h[s^t]
    float h[8];
    #pragma unroll
    for (int x = 0; x < 8; x++) {
        float f0 = (x & 4) ? (1.0f - p[0]) : p[0];
        float f1 = (x & 2) ? (1.0f - p[1]) : p[1];
        float f2 = (x & 1) ? (1.0f - p[2]) : p[2];
        h[x] = f0 * f1 * f2;
    }
    float beta[8];
    #pragma unroll
    for (int t = 0; t < 8; t++)
        beta[t] = 1.0f / (1.0f + expf(-(hp * (scale * dot[14 + t]) + sbeta[t])));

    float* Mo = &g_M[bn * 64];
    #pragma unroll
    for (int s = 0; s < 8; s++)
        #pragma unroll
        for (int t = 0; t < 8; t++)
            Mo[s * 8 + t] = h[s ^ t] + beta[t] * wpre[s];
}

// ---------------------------------------------------------------------------
// Kernel C: out[t,d] = sum_s M[s][t] * r[s,d].  grid=(BN, 2). fp32 residuals.
// ---------------------------------------------------------------------------
__global__ __launch_bounds__(256) void k_apply(const float* __restrict__ resid,
                                               float* __restrict__ out) {
    const int bn = blockIdx.x;
    const int b = bn >> 10, n = bn & 1023;

    __shared__ float Ms[64];
    if (threadIdx.x < 64) Ms[threadIdx.x] = g_M[bn * 64 + threadIdx.x];
    __syncthreads();

    float M[64];
    #pragma unroll
    for (int i = 0; i < 64; i++) M[i] = Ms[i];

    const size_t base = (size_t)b * 16777216u + (size_t)n * 2048u;
    const int d = blockIdx.y * 1024 + threadIdx.x * 4;

    float4 acc[8];
    #pragma unroll
    for (int t = 0; t < 8; t++) acc[t] = make_float4(0.f, 0.f, 0.f, 0.f);

    #pragma unroll
    for (int s = 0; s < 8; s++) {
        float4 r4 = *reinterpret_cast<const float4*>(resid + base + (size_t)s * 2097152u + d);
        #pragma unroll
        for (int t = 0; t < 8; t++) {
            float m = M[s * 8 + t];
            acc[t].x += m * r4.x;
            acc[t].y += m * r4.y;
            acc[t].z += m * r4.z;
            acc[t].w += m * r4.w;
        }
    }
    #pragma unroll
    for (int t = 0; t < 8; t++)
        *reinterpret_cast<float4*>(out + base + (size_t)t * 2097152u + d) = acc[t];
}

// ---------------------------------------------------------------------------
extern "C" void kernel_launch(void* const* d_in, const int* in_sizes, int n_in,
                              void* d_out, int out_size) {
    const float* resid  = (const float*)d_in[0];   // residuals (B*S, N, D)
    const float* gamma  = (const float*)d_in[1];   // (S*D,)
    const float* salpha = (const float*)d_in[2];   // (S+T,) = 14
    const float* Wa     = (const float*)d_in[3];   // (S*D, 14)
    const float* pbs    = (const float*)d_in[4];   // (1,)
    const float* rs     = (const float*)d_in[5];   // (1,)
    const float* sbeta  = (const float*)d_in[6];   // (S,) = 8
    const float* Wb     = (const float*)d_in[7];   // (S*D, 8)
    const float* hps    = (const float*)d_in[8];   // scalar
    float* out = (float*)d_out;

    k_prepW<<<(KT_TOT * 6 * 32 + 255) / 256, 256>>>(gamma, Wa, Wb);
    k_reduce<<<dim3(MT, KC), 256>>>(resid);
    k_mix<<<BN / 256, 256>>>(salpha, pbs, rs, sbeta, hps);
    k_apply<<<dim3(BN, 2), 256>>>(resid, out);
}